// round 1
// baseline (speedup 1.0000x reference)
#include <cuda_runtime.h>
#include <math.h>

// Problem constants
#define S   128   // sequence length
#define Dm  256   // model dim
#define H   8     // heads
#define HD  32    // head dim
#define KF  44    // feature expansion order (truncated exp(ab) series)
#define KP  45    // padded leading dim for psi in smem (45 coprime with 32 -> conflict-free)

// Device scratch (allocation-free rule: __device__ globals)
__device__ float g_xln[H][S][HD];   // LayerNorm'ed per-head activations
__device__ float g_psi[H][S][KF];   // feature vectors  psi_k = sum_e a^k e^{-a^2/2}/sqrt(k!)
__device__ float g_cat[S][Dm];      // concatenated head outputs

__device__ __forceinline__ float warpsum(float v) {
    #pragma unroll
    for (int o = 16; o > 0; o >>= 1) v += __shfl_xor_sync(0xffffffffu, v, o);
    return v;
}
__device__ __forceinline__ float warpmax(float v) {
    #pragma unroll
    for (int o = 16; o > 0; o >>= 1) v = fmaxf(v, __shfl_xor_sync(0xffffffffu, v, o));
    return v;
}

// ---------------------------------------------------------------------------
// Kernel A: X1 = inputs @ w_in^T + b_in (per-head 32-col slice), then
//           LayerNorm over head_dim, then Gaussian feature expansion.
// grid: (4 token blocks, 8 heads), 256 threads.
// ---------------------------------------------------------------------------
__global__ void __launch_bounds__(256) kA(const float* __restrict__ inp,
                                          const float* __restrict__ w_in,
                                          const float* __restrict__ b_in,
                                          const float* __restrict__ ln_g,
                                          const float* __restrict__ ln_b) {
    __shared__ float As[32][65];   // inputs tile  [token][k-chunk]
    __shared__ float Bs[32][65];   // weight tile  [out-col][k-chunk]
    __shared__ float Cs[32][33];   // X1 tile      [token][head-col]

    const int tb = blockIdx.x;          // token block (32 tokens)
    const int h  = blockIdx.y;          // head
    const int tid = threadIdx.x;
    const int lane = tid & 31, wid = tid >> 5;
    const int t0 = tb * 32;

    float acc[4] = {0.f, 0.f, 0.f, 0.f};

    for (int kc = 0; kc < Dm; kc += 64) {
        for (int i = tid; i < 32 * 64; i += 256) {
            int r = i >> 6, c = i & 63;
            As[r][c] = inp[(t0 + r) * Dm + kc + c];
            Bs[r][c] = w_in[(h * HD + r) * Dm + kc + c];
        }
        __syncthreads();
        #pragma unroll
        for (int kk = 0; kk < 64; ++kk) {
            float b = Bs[lane][kk];
            #pragma unroll
            for (int q = 0; q < 4; ++q)
                acc[q] = fmaf(As[wid + 8 * q][kk], b, acc[q]);
        }
        __syncthreads();
    }

    const float bias = b_in[h * HD + lane];
    #pragma unroll
    for (int q = 0; q < 4; ++q) Cs[wid + 8 * q][lane] = acc[q] + bias;
    __syncthreads();

    // LayerNorm + features: warp `wid` handles local tokens 4*wid .. 4*wid+3
    const float gg = ln_g[lane], bb = ln_b[lane];
    for (int ti = 0; ti < 4; ++ti) {
        const int tl = wid * 4 + ti;
        const float v  = Cs[tl][lane];
        const float mu = warpsum(v) * (1.0f / 32.0f);
        const float d  = v - mu;
        const float var = warpsum(d * d) * (1.0f / 32.0f);
        const float y = d * rsqrtf(var + 1e-5f) * gg + bb;
        const int tg = t0 + tl;
        g_xln[h][tg][lane] = y;

        // feature recurrence: t_k = t_{k-1} * y / sqrt(k),  t_0 = exp(-y^2/2)
        float t = expf(-0.5f * y * y);
        float s = warpsum(t);
        if (lane == 0) g_psi[h][tg][0] = s;
        for (int k = 1; k < KF; ++k) {
            t *= y * rsqrtf((float)k);
            s = warpsum(t);
            if (lane == 0) g_psi[h][tg][k] = s;
        }
    }
}

// ---------------------------------------------------------------------------
// Kernel B: per-head scores = (Psi Psi^T)/HD, softmax over t, out = P @ xln.
// grid: (4 row blocks, 8 heads), 256 threads.
// ---------------------------------------------------------------------------
__global__ void __launch_bounds__(256) kB() {
    __shared__ float Sc[32][128];          // scores / probabilities
    __shared__ float buf[128 * KP];        // phase1: Psi [128][45]; phase2: Xln [128][33]

    const int rb = blockIdx.x;             // row block (32 query rows)
    const int h  = blockIdx.y;
    const int tid = threadIdx.x;
    const int lane = tid & 31, wid = tid >> 5;
    const int s0 = rb * 32;

    // load Psi[h] (128 x 44) -> padded smem (ld=45)
    const float* psi = &g_psi[h][0][0];
    for (int i = tid; i < S * KF; i += 256) {
        int r = i / KF, c = i - r * KF;
        buf[r * KP + c] = psi[i];
    }
    __syncthreads();

    // scores: thread handles s = s0 + wid*4 + si, t = lane + 32*tj
    float acc[4][4];
    #pragma unroll
    for (int a = 0; a < 4; ++a)
        #pragma unroll
        for (int b = 0; b < 4; ++b) acc[a][b] = 0.f;

    for (int k = 0; k < KF; ++k) {
        float rs[4], rt[4];
        #pragma unroll
        for (int si = 0; si < 4; ++si) rs[si] = buf[(s0 + wid * 4 + si) * KP + k];
        #pragma unroll
        for (int tj = 0; tj < 4; ++tj) rt[tj] = buf[(lane + 32 * tj) * KP + k];
        #pragma unroll
        for (int si = 0; si < 4; ++si)
            #pragma unroll
            for (int tj = 0; tj < 4; ++tj)
                acc[si][tj] = fmaf(rs[si], rt[tj], acc[si][tj]);
    }
    #pragma unroll
    for (int si = 0; si < 4; ++si)
        #pragma unroll
        for (int tj = 0; tj < 4; ++tj)
            Sc[wid * 4 + si][lane + 32 * tj] = acc[si][tj] * (1.0f / 32.0f);
    __syncthreads();

    // softmax: warp `wid` handles rows wid*4 .. +3, each lane 4 columns
    for (int ri = 0; ri < 4; ++ri) {
        const int r = wid * 4 + ri;
        float v[4];
        #pragma unroll
        for (int j = 0; j < 4; ++j) v[j] = Sc[r][lane + 32 * j];
        float m = fmaxf(fmaxf(v[0], v[1]), fmaxf(v[2], v[3]));
        m = warpmax(m);
        float sum = 0.f;
        #pragma unroll
        for (int j = 0; j < 4; ++j) { v[j] = __expf(v[j] - m); sum += v[j]; }
        sum = warpsum(sum);
        const float inv = 1.0f / sum;
        #pragma unroll
        for (int j = 0; j < 4; ++j) Sc[r][lane + 32 * j] = v[j] * inv;
    }
    __syncthreads();

    // reload buf with Xln[h] (128 x 32, ld=33)
    const float* xl = &g_xln[h][0][0];
    for (int i = tid; i < S * HD; i += 256) {
        int r = i >> 5, c = i & 31;
        buf[r * 33 + c] = xl[i];
    }
    __syncthreads();

    // out[s][e] = sum_t P[s][t] * Xln[t][e];  thread: s = s0+wid*4+si, e = lane
    float o[4] = {0.f, 0.f, 0.f, 0.f};
    for (int t = 0; t < S; ++t) {
        const float xt = buf[t * 33 + lane];
        #pragma unroll
        for (int si = 0; si < 4; ++si)
            o[si] = fmaf(Sc[wid * 4 + si][t], xt, o[si]);
    }
    #pragma unroll
    for (int si = 0; si < 4; ++si)
        g_cat[s0 + wid * 4 + si][h * HD + lane] = o[si];
}

// ---------------------------------------------------------------------------
// Kernel C: out = cat @ w_out^T + b_out.
// grid: (4 token blocks, 8 out-dim blocks), 256 threads.
// ---------------------------------------------------------------------------
__global__ void __launch_bounds__(256) kC(const float* __restrict__ w_out,
                                          const float* __restrict__ b_out,
                                          float* __restrict__ out) {
    __shared__ float As[32][65];
    __shared__ float Bs[32][65];

    const int tb = blockIdx.x, db = blockIdx.y;
    const int tid = threadIdx.x;
    const int lane = tid & 31, wid = tid >> 5;
    const int t0 = tb * 32, d0 = db * 32;

    float acc[4] = {0.f, 0.f, 0.f, 0.f};

    for (int kc = 0; kc < Dm; kc += 64) {
        for (int i = tid; i < 32 * 64; i += 256) {
            int r = i >> 6, c = i & 63;
            As[r][c] = g_cat[t0 + r][kc + c];
            Bs[r][c] = w_out[(d0 + r) * Dm + kc + c];
        }
        __syncthreads();
        #pragma unroll
        for (int kk = 0; kk < 64; ++kk) {
            float b = Bs[lane][kk];
            #pragma unroll
            for (int q = 0; q < 4; ++q)
                acc[q] = fmaf(As[wid + 8 * q][kk], b, acc[q]);
        }
        __syncthreads();
    }

    const float bias = b_out[d0 + lane];
    #pragma unroll
    for (int q = 0; q < 4; ++q)
        out[(t0 + wid + 8 * q) * Dm + d0 + lane] = acc[q] + bias;
}

// ---------------------------------------------------------------------------
extern "C" void kernel_launch(void* const* d_in, const int* in_sizes, int n_in,
                              void* d_out, int out_size) {
    const float* inp   = (const float*)d_in[0];
    const float* w_in  = (const float*)d_in[1];
    const float* b_in  = (const float*)d_in[2];
    const float* ln_g  = (const float*)d_in[3];
    const float* ln_b  = (const float*)d_in[4];
    const float* w_out = (const float*)d_in[5];
    const float* b_out = (const float*)d_in[6];
    float* out = (float*)d_out;

    kA<<<dim3(4, 8), 256>>>(inp, w_in, b_in, ln_g, ln_b);
    kB<<<dim3(4, 8), 256>>>();
    kC<<<dim3(4, 8), 256>>>(w_out, b_out, out);
}

// round 2
// speedup vs baseline: 2.1100x; 2.1100x over previous
#include <cuda_runtime.h>
#include <math.h>

#define S    128
#define Dm   256
#define H    8
#define HD   32
#define KF   44          // feature order (44 = 11 float4 groups exactly)
#define KPAD 48          // smem leading dim for psi in kB (mult of 4)
#define BT   8           // tokens per block (kA, kC)

// Device scratch
__device__ float g_xln[H][S][HD];
__device__ float g_psi[H][S][KF];
__device__ float g_cat[S][Dm];

__device__ __forceinline__ float warpsum(float v) {
    #pragma unroll
    for (int o = 16; o > 0; o >>= 1) v += __shfl_xor_sync(0xffffffffu, v, o);
    return v;
}
__device__ __forceinline__ float warpmax(float v) {
    #pragma unroll
    for (int o = 16; o > 0; o >>= 1) v = fmaxf(v, __shfl_xor_sync(0xffffffffu, v, o));
    return v;
}

// 1/sqrt(k) literals (fold into FFMA immediates; no MUFU in the chain)
__device__ __constant__ float c_rsq[KF] = {
    1.0f,          1.0f,          0.70710678f,   0.57735027f,
    0.5f,          0.44721360f,   0.40824829f,   0.37796447f,
    0.35355339f,   0.33333333f,   0.31622777f,   0.30151134f,
    0.28867513f,   0.27735010f,   0.26726124f,   0.25819889f,
    0.25f,         0.24253563f,   0.23570226f,   0.22941573f,
    0.22360680f,   0.21821789f,   0.21320072f,   0.20851441f,
    0.20412415f,   0.2f,          0.19611614f,   0.19245009f,
    0.18898224f,   0.18569534f,   0.18257419f,   0.17960530f,
    0.17677670f,   0.17407766f,   0.17149859f,   0.16903085f,
    0.16666667f,   0.16439899f,   0.16222142f,   0.16012815f,
    0.15811388f,   0.15617376f,   0.15430335f,   0.15249857f
};

// ---------------------------------------------------------------------------
// Kernel A: X1 = inp @ w_in^T + b_in (per-head 32 cols), LayerNorm, features.
// grid (16 token-blocks, 8 heads) x 256 threads. warp = token, lane = col.
// ---------------------------------------------------------------------------
__global__ void __launch_bounds__(256) kA(const float* __restrict__ inp,
                                          const float* __restrict__ w_in,
                                          const float* __restrict__ b_in,
                                          const float* __restrict__ ln_g,
                                          const float* __restrict__ ln_b) {
    __shared__ float As[BT][260];    // 8 tokens x 256 (pad 260: 16B-chunk stride 65, odd)
    __shared__ float Bs[HD][260];    // 32 head-cols x 256

    const int t0  = blockIdx.x * BT;
    const int h   = blockIdx.y;
    const int tid = threadIdx.x;
    const int lane = tid & 31, wid = tid >> 5;

    // single-shot tile loads (whole K at once, max MLP)
    for (int i = tid; i < BT * 64; i += 256) {      // 512 float4
        int r = i >> 6, c4 = i & 63;
        *(float4*)&As[r][c4 * 4] = *(const float4*)&inp[(t0 + r) * Dm + c4 * 4];
    }
    for (int i = tid; i < HD * 64; i += 256) {      // 2048 float4
        int r = i >> 6, c4 = i & 63;
        *(float4*)&Bs[r][c4 * 4] = *(const float4*)&w_in[(h * HD + r) * Dm + c4 * 4];
    }
    __syncthreads();

    // GEMM: token = wid, col = lane
    float acc = 0.f;
    #pragma unroll
    for (int k4 = 0; k4 < 64; ++k4) {
        float4 a = *(float4*)&As[wid][k4 * 4];      // broadcast
        float4 b = *(float4*)&Bs[lane][k4 * 4];     // conflict-free
        acc = fmaf(a.x, b.x, acc);
        acc = fmaf(a.y, b.y, acc);
        acc = fmaf(a.z, b.z, acc);
        acc = fmaf(a.w, b.w, acc);
    }
    acc += b_in[h * HD + lane];

    // LayerNorm over head_dim (warp holds the token's full vector)
    const float mu  = warpsum(acc) * (1.0f / 32.0f);
    const float d   = acc - mu;
    const float var = warpsum(d * d) * (1.0f / 32.0f);
    const float y   = d * rsqrtf(var + 1e-5f) * ln_g[lane] + ln_b[lane];
    const int   tg  = t0 + wid;
    g_xln[h][tg][lane] = y;

    // Feature expansion: t_k = t_{k-1} * y / sqrt(k), t_0 = exp(-y^2/2)
    float t[KF];
    t[0] = __expf(-0.5f * y * y);
    #pragma unroll
    for (int k = 1; k < KF; ++k) t[k] = t[k - 1] * y * c_rsq[k];

    // ONE batched butterfly over the whole vector (independent shuffles)
    #pragma unroll
    for (int o = 16; o > 0; o >>= 1) {
        #pragma unroll
        for (int k = 0; k < KF; ++k) t[k] += __shfl_xor_sync(0xffffffffu, t[k], o);
    }
    if (lane == 0) {
        float* dst = &g_psi[h][tg][0];
        #pragma unroll
        for (int k4 = 0; k4 < KF / 4; ++k4) {
            float4 v = make_float4(t[k4 * 4], t[k4 * 4 + 1], t[k4 * 4 + 2], t[k4 * 4 + 3]);
            *(float4*)&dst[k4 * 4] = v;
        }
    }
}

// ---------------------------------------------------------------------------
// Kernel B: scores = Psi Psi^T / HD, softmax, out = P @ Xln.
// grid (8 row-blocks of 16, 8 heads) x 256 threads.
// ---------------------------------------------------------------------------
__global__ void __launch_bounds__(256) kB() {
    __shared__ float Ps[S][KPAD];    // 24576 B
    __shared__ float Xs[S][HD];      // 16384 B (stride 32: Xs[t][lane] conflict-free)
    __shared__ float Sc[16][S];      //  8192 B   (total = 49152 B)

    const int s0  = blockIdx.x * 16;
    const int h   = blockIdx.y;
    const int tid = threadIdx.x;
    const int lane = tid & 31, wid = tid >> 5;

    // load Psi[h] (128 x 44 = 1408 float4)
    const float* psi = &g_psi[h][0][0];
    for (int i = tid; i < S * (KF / 4); i += 256) {
        int r = i / (KF / 4), c4 = i - r * (KF / 4);
        *(float4*)&Ps[r][c4 * 4] = *(const float4*)&psi[r * KF + c4 * 4];
    }
    // load Xln[h] (128 x 32 = 1024 float4)
    const float* xl = &g_xln[h][0][0];
    for (int i = tid; i < S * (HD / 4); i += 256) {
        int r = i >> 3, c4 = i & 7;
        *(float4*)&Xs[r][c4 * 4] = *(const float4*)&xl[r * HD + c4 * 4];
    }
    __syncthreads();

    // scores: s = s0 + wid*2 + si (si<2), t = lane + 32*tj (tj<4)
    float acc[2][4];
    #pragma unroll
    for (int a = 0; a < 2; ++a)
        #pragma unroll
        for (int b = 0; b < 4; ++b) acc[a][b] = 0.f;

    #pragma unroll
    for (int kg = 0; kg < KF / 4; ++kg) {
        float4 rs[2], rt[4];
        #pragma unroll
        for (int si = 0; si < 2; ++si) rs[si] = *(float4*)&Ps[s0 + wid * 2 + si][kg * 4];
        #pragma unroll
        for (int tj = 0; tj < 4; ++tj) rt[tj] = *(float4*)&Ps[lane + 32 * tj][kg * 4];
        #pragma unroll
        for (int si = 0; si < 2; ++si)
            #pragma unroll
            for (int tj = 0; tj < 4; ++tj) {
                acc[si][tj] = fmaf(rs[si].x, rt[tj].x, acc[si][tj]);
                acc[si][tj] = fmaf(rs[si].y, rt[tj].y, acc[si][tj]);
                acc[si][tj] = fmaf(rs[si].z, rt[tj].z, acc[si][tj]);
                acc[si][tj] = fmaf(rs[si].w, rt[tj].w, acc[si][tj]);
            }
    }
    #pragma unroll
    for (int si = 0; si < 2; ++si)
        #pragma unroll
        for (int tj = 0; tj < 4; ++tj)
            Sc[wid * 2 + si][lane + 32 * tj] = acc[si][tj] * (1.0f / 32.0f);
    __syncthreads();

    // softmax: warp handles rows wid*2, wid*2+1
    #pragma unroll
    for (int ri = 0; ri < 2; ++ri) {
        const int r = wid * 2 + ri;
        float v[4];
        #pragma unroll
        for (int j = 0; j < 4; ++j) v[j] = Sc[r][lane + 32 * j];
        float m = fmaxf(fmaxf(v[0], v[1]), fmaxf(v[2], v[3]));
        m = warpmax(m);
        float sum = 0.f;
        #pragma unroll
        for (int j = 0; j < 4; ++j) { v[j] = __expf(v[j] - m); sum += v[j]; }
        sum = warpsum(sum);
        const float inv = 1.0f / sum;
        #pragma unroll
        for (int j = 0; j < 4; ++j) Sc[r][lane + 32 * j] = v[j] * inv;
    }
    __syncthreads();

    // AV: out[s][e] = sum_t P[s][t] Xln[t][e];  s = s0+wid*2+si, e = lane
    float o[2] = {0.f, 0.f};
    #pragma unroll 4
    for (int t4 = 0; t4 < S / 4; ++t4) {
        float xt0 = Xs[t4 * 4 + 0][lane];
        float xt1 = Xs[t4 * 4 + 1][lane];
        float xt2 = Xs[t4 * 4 + 2][lane];
        float xt3 = Xs[t4 * 4 + 3][lane];
        float4 p0 = *(float4*)&Sc[wid * 2 + 0][t4 * 4];
        float4 p1 = *(float4*)&Sc[wid * 2 + 1][t4 * 4];
        o[0] = fmaf(p0.x, xt0, o[0]); o[0] = fmaf(p0.y, xt1, o[0]);
        o[0] = fmaf(p0.z, xt2, o[0]); o[0] = fmaf(p0.w, xt3, o[0]);
        o[1] = fmaf(p1.x, xt0, o[1]); o[1] = fmaf(p1.y, xt1, o[1]);
        o[1] = fmaf(p1.z, xt2, o[1]); o[1] = fmaf(p1.w, xt3, o[1]);
    }
    g_cat[s0 + wid * 2 + 0][h * HD + lane] = o[0];
    g_cat[s0 + wid * 2 + 1][h * HD + lane] = o[1];
}

// ---------------------------------------------------------------------------
// Kernel C: out = cat @ w_out^T + b_out.
// grid (16 token-blocks, 8 col-blocks) x 256 threads. warp = token, lane = col.
// ---------------------------------------------------------------------------
__global__ void __launch_bounds__(256) kC(const float* __restrict__ w_out,
                                          const float* __restrict__ b_out,
                                          float* __restrict__ out) {
    __shared__ float As[BT][260];
    __shared__ float Bs[HD][260];

    const int t0  = blockIdx.x * BT;
    const int d0  = blockIdx.y * 32;
    const int tid = threadIdx.x;
    const int lane = tid & 31, wid = tid >> 5;

    for (int i = tid; i < BT * 64; i += 256) {
        int r = i >> 6, c4 = i & 63;
        *(float4*)&As[r][c4 * 4] = *(const float4*)&g_cat[t0 + r][c4 * 4];
    }
    for (int i = tid; i < 32 * 64; i += 256) {
        int r = i >> 6, c4 = i & 63;
        *(float4*)&Bs[r][c4 * 4] = *(const float4*)&w_out[(d0 + r) * Dm + c4 * 4];
    }
    __syncthreads();

    float acc = 0.f;
    #pragma unroll
    for (int k4 = 0; k4 < 64; ++k4) {
        float4 a = *(float4*)&As[wid][k4 * 4];
        float4 b = *(float4*)&Bs[lane][k4 * 4];
        acc = fmaf(a.x, b.x, acc);
        acc = fmaf(a.y, b.y, acc);
        acc = fmaf(a.z, b.z, acc);
        acc = fmaf(a.w, b.w, acc);
    }
    out[(t0 + wid) * Dm + d0 + lane] = acc + b_out[d0 + lane];
}

// ---------------------------------------------------------------------------
extern "C" void kernel_launch(void* const* d_in, const int* in_sizes, int n_in,
                              void* d_out, int out_size) {
    const float* inp   = (const float*)d_in[0];
    const float* w_in  = (const float*)d_in[1];
    const float* b_in  = (const float*)d_in[2];
    const float* ln_g  = (const float*)d_in[3];
    const float* ln_b  = (const float*)d_in[4];
    const float* w_out = (const float*)d_in[5];
    const float* b_out = (const float*)d_in[6];
    float* out = (float*)d_out;

    kA<<<dim3(16, 8), 256>>>(inp, w_in, b_in, ln_g, ln_b);
    kB<<<dim3(8, 8), 256>>>();
    kC<<<dim3(16, 8), 256>>>(w_out, b_out, out);
}

// round 3
// speedup vs baseline: 2.3135x; 1.0965x over previous
#include <cuda_runtime.h>
#include <math.h>

#define S    128
#define Dm   256
#define H    8
#define HD   32
#define KF   44
#define KPAD 48
#define BT   8           // tokens per block (kA, kC)

// 1/sqrt(24!)
#define RSF24 1.2695437e-12f

// Device scratch
__device__ float g_xln[H][S][HD];
__device__ float g_psi[H][S][KF];
__device__ float g_cat[S][Dm];

__device__ __forceinline__ float warpsum(float v) {
    #pragma unroll
    for (int o = 16; o > 0; o >>= 1) v += __shfl_xor_sync(0xffffffffu, v, o);
    return v;
}
__device__ __forceinline__ float warpmax(float v) {
    #pragma unroll
    for (int o = 16; o > 0; o >>= 1) v = fmaxf(v, __shfl_xor_sync(0xffffffffu, v, o));
    return v;
}

// 1/sqrt(k)
__device__ __constant__ float c_rsq[KF] = {
    1.0f,          1.0f,          0.70710678f,   0.57735027f,
    0.5f,          0.44721360f,   0.40824829f,   0.37796447f,
    0.35355339f,   0.33333333f,   0.31622777f,   0.30151134f,
    0.28867513f,   0.27735010f,   0.26726124f,   0.25819889f,
    0.25f,         0.24253563f,   0.23570226f,   0.22941573f,
    0.22360680f,   0.21821789f,   0.21320072f,   0.20851441f,
    0.20412415f,   0.2f,          0.19611614f,   0.19245009f,
    0.18898224f,   0.18569534f,   0.18257419f,   0.17960530f,
    0.17677670f,   0.17407766f,   0.17149859f,   0.16903085f,
    0.16666667f,   0.16439899f,   0.16222142f,   0.16012815f,
    0.15811388f,   0.15617376f,   0.15430335f,   0.15249857f
};

// Reduce-and-store one chunk of 8 feature values. cur = value at k = kbase.
// Returns cur advanced to k = kbase+7. Max ~10 live floats -> no spills.
__device__ __forceinline__ float feat_chunk8(float cur, float y, int kbase,
                                             float* dst, int lane) {
    float v0 = cur, v1, v2, v3, v4, v5, v6, v7;
    cur *= y * c_rsq[kbase + 1]; v1 = cur;
    cur *= y * c_rsq[kbase + 2]; v2 = cur;
    cur *= y * c_rsq[kbase + 3]; v3 = cur;
    cur *= y * c_rsq[kbase + 4]; v4 = cur;
    cur *= y * c_rsq[kbase + 5]; v5 = cur;
    cur *= y * c_rsq[kbase + 6]; v6 = cur;
    cur *= y * c_rsq[kbase + 7]; v7 = cur;
    #pragma unroll
    for (int o = 16; o > 0; o >>= 1) {
        v0 += __shfl_xor_sync(0xffffffffu, v0, o);
        v1 += __shfl_xor_sync(0xffffffffu, v1, o);
        v2 += __shfl_xor_sync(0xffffffffu, v2, o);
        v3 += __shfl_xor_sync(0xffffffffu, v3, o);
        v4 += __shfl_xor_sync(0xffffffffu, v4, o);
        v5 += __shfl_xor_sync(0xffffffffu, v5, o);
        v6 += __shfl_xor_sync(0xffffffffu, v6, o);
        v7 += __shfl_xor_sync(0xffffffffu, v7, o);
    }
    if (lane == 0) {
        *(float4*)&dst[kbase]     = make_float4(v0, v1, v2, v3);
        *(float4*)&dst[kbase + 4] = make_float4(v4, v5, v6, v7);
    }
    return cur;
}

__device__ __forceinline__ void feat_chunk4(float cur, float y, int kbase,
                                            float* dst, int lane) {
    float v0 = cur, v1, v2, v3;
    cur *= y * c_rsq[kbase + 1]; v1 = cur;
    cur *= y * c_rsq[kbase + 2]; v2 = cur;
    cur *= y * c_rsq[kbase + 3]; v3 = cur;
    #pragma unroll
    for (int o = 16; o > 0; o >>= 1) {
        v0 += __shfl_xor_sync(0xffffffffu, v0, o);
        v1 += __shfl_xor_sync(0xffffffffu, v1, o);
        v2 += __shfl_xor_sync(0xffffffffu, v2, o);
        v3 += __shfl_xor_sync(0xffffffffu, v3, o);
    }
    if (lane == 0)
        *(float4*)&dst[kbase] = make_float4(v0, v1, v2, v3);
}

// ---------------------------------------------------------------------------
// Kernel A: proj + LayerNorm + features. 512 threads, grid (16 tb, 8 heads).
// GEMM: thread = (col=lane, 2 tokens, K-quarter). Features: 2 warps per token.
// ---------------------------------------------------------------------------
__global__ void __launch_bounds__(512) kA(const float* __restrict__ inp,
                                          const float* __restrict__ w_in,
                                          const float* __restrict__ b_in,
                                          const float* __restrict__ ln_g,
                                          const float* __restrict__ ln_b) {
    __shared__ float As[BT][260];
    __shared__ float Bs[HD][260];
    __shared__ float Pp[4][BT][HD];   // K-quarter partials

    const int t0  = blockIdx.x * BT;
    const int h   = blockIdx.y;
    const int tid = threadIdx.x;
    const int lane = tid & 31, wid = tid >> 5;   // 16 warps

    for (int i = tid; i < BT * 64; i += 512) {
        int r = i >> 6, c4 = i & 63;
        *(float4*)&As[r][c4 * 4] = *(const float4*)&inp[(t0 + r) * Dm + c4 * 4];
    }
    for (int i = tid; i < HD * 64; i += 512) {
        int r = i >> 6, c4 = i & 63;
        *(float4*)&Bs[r][c4 * 4] = *(const float4*)&w_in[(h * HD + r) * Dm + c4 * 4];
    }
    __syncthreads();

    // GEMM: kq = K-quarter (64 wide), tp = token pair
    {
        const int kq = wid >> 2, tp = wid & 3;
        float a0 = 0.f, a1 = 0.f;
        #pragma unroll
        for (int k4 = kq * 16; k4 < kq * 16 + 16; ++k4) {
            float4 b  = *(float4*)&Bs[lane][k4 * 4];
            float4 x0 = *(float4*)&As[tp * 2 + 0][k4 * 4];
            float4 x1 = *(float4*)&As[tp * 2 + 1][k4 * 4];
            a0 = fmaf(x0.x, b.x, a0); a0 = fmaf(x0.y, b.y, a0);
            a0 = fmaf(x0.z, b.z, a0); a0 = fmaf(x0.w, b.w, a0);
            a1 = fmaf(x1.x, b.x, a1); a1 = fmaf(x1.y, b.y, a1);
            a1 = fmaf(x1.z, b.z, a1); a1 = fmaf(x1.w, b.w, a1);
        }
        Pp[kq][tp * 2 + 0][lane] = a0;
        Pp[kq][tp * 2 + 1][lane] = a1;
    }
    __syncthreads();

    // Reduce + LN (computed redundantly by both warps of each token)
    const int tok = wid & 7;
    float acc = Pp[0][tok][lane] + Pp[1][tok][lane]
              + Pp[2][tok][lane] + Pp[3][tok][lane]
              + b_in[h * HD + lane];

    const float mu  = warpsum(acc) * (1.0f / 32.0f);
    const float d   = acc - mu;
    const float var = warpsum(d * d) * (1.0f / 32.0f);
    const float y   = d * rsqrtf(var + 1e-5f) * ln_g[lane] + ln_b[lane];
    const int   tg  = t0 + tok;
    if (wid < 8) g_xln[h][tg][lane] = y;

    // Features: warps 0-7 do k in [0,24), warps 8-15 do k in [24,44)
    float* dst = &g_psi[h][tg][0];
    const float t0e = __expf(-0.5f * y * y);
    if (wid < 8) {
        float cur = t0e;                       // k = 0
        cur = feat_chunk8(cur, y, 0, dst, lane);
        cur *= y * c_rsq[8];
        cur = feat_chunk8(cur, y, 8, dst, lane);
        cur *= y * c_rsq[16];
        feat_chunk8(cur, y, 16, dst, lane);
    } else {
        // jump directly to k = 24: t24 = t0 * y^24 / sqrt(24!)
        const float y2 = y * y, y4 = y2 * y2, y8 = y4 * y4, y16 = y8 * y8;
        float cur = t0e * (y16 * y8) * RSF24;  // k = 24
        cur = feat_chunk8(cur, y, 24, dst, lane);
        cur *= y * c_rsq[32];
        cur = feat_chunk8(cur, y, 32, dst, lane);
        cur *= y * c_rsq[40];
        feat_chunk4(cur, y, 40, dst, lane);
    }
}

// ---------------------------------------------------------------------------
// Kernel B: scores = Psi Psi^T / HD, softmax, out = P @ Xln.
// grid (8 row-blocks of 16, 8 heads) x 256 threads.
// ---------------------------------------------------------------------------
__global__ void __launch_bounds__(256) kB() {
    __shared__ float Ps[S][KPAD];
    __shared__ float Xs[S][HD];
    __shared__ float Sc[16][S];

    const int s0  = blockIdx.x * 16;
    const int h   = blockIdx.y;
    const int tid = threadIdx.x;
    const int lane = tid & 31, wid = tid >> 5;

    const float* psi = &g_psi[h][0][0];
    for (int i = tid; i < S * (KF / 4); i += 256) {
        int r = i / (KF / 4), c4 = i - r * (KF / 4);
        *(float4*)&Ps[r][c4 * 4] = *(const float4*)&psi[r * KF + c4 * 4];
    }
    const float* xl = &g_xln[h][0][0];
    for (int i = tid; i < S * (HD / 4); i += 256) {
        int r = i >> 3, c4 = i & 7;
        *(float4*)&Xs[r][c4 * 4] = *(const float4*)&xl[r * HD + c4 * 4];
    }
    __syncthreads();

    float acc[2][4];
    #pragma unroll
    for (int a = 0; a < 2; ++a)
        #pragma unroll
        for (int b = 0; b < 4; ++b) acc[a][b] = 0.f;

    #pragma unroll
    for (int kg = 0; kg < KF / 4; ++kg) {
        float4 rs[2], rt[4];
        #pragma unroll
        for (int si = 0; si < 2; ++si) rs[si] = *(float4*)&Ps[s0 + wid * 2 + si][kg * 4];
        #pragma unroll
        for (int tj = 0; tj < 4; ++tj) rt[tj] = *(float4*)&Ps[lane + 32 * tj][kg * 4];
        #pragma unroll
        for (int si = 0; si < 2; ++si)
            #pragma unroll
            for (int tj = 0; tj < 4; ++tj) {
                acc[si][tj] = fmaf(rs[si].x, rt[tj].x, acc[si][tj]);
                acc[si][tj] = fmaf(rs[si].y, rt[tj].y, acc[si][tj]);
                acc[si][tj] = fmaf(rs[si].z, rt[tj].z, acc[si][tj]);
                acc[si][tj] = fmaf(rs[si].w, rt[tj].w, acc[si][tj]);
            }
    }
    #pragma unroll
    for (int si = 0; si < 2; ++si)
        #pragma unroll
        for (int tj = 0; tj < 4; ++tj)
            Sc[wid * 2 + si][lane + 32 * tj] = acc[si][tj] * (1.0f / 32.0f);
    __syncthreads();

    #pragma unroll
    for (int ri = 0; ri < 2; ++ri) {
        const int r = wid * 2 + ri;
        float v[4];
        #pragma unroll
        for (int j = 0; j < 4; ++j) v[j] = Sc[r][lane + 32 * j];
        float m = fmaxf(fmaxf(v[0], v[1]), fmaxf(v[2], v[3]));
        m = warpmax(m);
        float sum = 0.f;
        #pragma unroll
        for (int j = 0; j < 4; ++j) { v[j] = __expf(v[j] - m); sum += v[j]; }
        sum = warpsum(sum);
        const float inv = 1.0f / sum;
        #pragma unroll
        for (int j = 0; j < 4; ++j) Sc[r][lane + 32 * j] = v[j] * inv;
    }
    __syncthreads();

    float o[2] = {0.f, 0.f};
    #pragma unroll 4
    for (int t4 = 0; t4 < S / 4; ++t4) {
        float xt0 = Xs[t4 * 4 + 0][lane];
        float xt1 = Xs[t4 * 4 + 1][lane];
        float xt2 = Xs[t4 * 4 + 2][lane];
        float xt3 = Xs[t4 * 4 + 3][lane];
        float4 p0 = *(float4*)&Sc[wid * 2 + 0][t4 * 4];
        float4 p1 = *(float4*)&Sc[wid * 2 + 1][t4 * 4];
        o[0] = fmaf(p0.x, xt0, o[0]); o[0] = fmaf(p0.y, xt1, o[0]);
        o[0] = fmaf(p0.z, xt2, o[0]); o[0] = fmaf(p0.w, xt3, o[0]);
        o[1] = fmaf(p1.x, xt0, o[1]); o[1] = fmaf(p1.y, xt1, o[1]);
        o[1] = fmaf(p1.z, xt2, o[1]); o[1] = fmaf(p1.w, xt3, o[1]);
    }
    g_cat[s0 + wid * 2 + 0][h * HD + lane] = o[0];
    g_cat[s0 + wid * 2 + 1][h * HD + lane] = o[1];
}

// ---------------------------------------------------------------------------
// Kernel C: out = cat @ w_out^T + b_out. Same GEMM structure as kA.
// grid (16 token-blocks, 8 col-blocks) x 512 threads.
// ---------------------------------------------------------------------------
__global__ void __launch_bounds__(512) kC(const float* __restrict__ w_out,
                                          const float* __restrict__ b_out,
                                          float* __restrict__ out) {
    __shared__ float As[BT][260];
    __shared__ float Bs[HD][260];
    __shared__ float Pp[4][BT][HD];

    const int t0  = blockIdx.x * BT;
    const int d0  = blockIdx.y * 32;
    const int tid = threadIdx.x;
    const int lane = tid & 31, wid = tid >> 5;

    for (int i = tid; i < BT * 64; i += 512) {
        int r = i >> 6, c4 = i & 63;
        *(float4*)&As[r][c4 * 4] = *(const float4*)&g_cat[t0 + r][c4 * 4];
    }
    for (int i = tid; i < HD * 64; i += 512) {
        int r = i >> 6, c4 = i & 63;
        *(float4*)&Bs[r][c4 * 4] = *(const float4*)&w_out[(d0 + r) * Dm + c4 * 4];
    }
    __syncthreads();

    {
        const int kq = wid >> 2, tp = wid & 3;
        float a0 = 0.f, a1 = 0.f;
        #pragma unroll
        for (int k4 = kq * 16; k4 < kq * 16 + 16; ++k4) {
            float4 b  = *(float4*)&Bs[lane][k4 * 4];
            float4 x0 = *(float4*)&As[tp * 2 + 0][k4 * 4];
            float4 x1 = *(float4*)&As[tp * 2 + 1][k4 * 4];
            a0 = fmaf(x0.x, b.x, a0); a0 = fmaf(x0.y, b.y, a0);
            a0 = fmaf(x0.z, b.z, a0); a0 = fmaf(x0.w, b.w, a0);
            a1 = fmaf(x1.x, b.x, a1); a1 = fmaf(x1.y, b.y, a1);
            a1 = fmaf(x1.z, b.z, a1); a1 = fmaf(x1.w, b.w, a1);
        }
        Pp[kq][tp * 2 + 0][lane] = a0;
        Pp[kq][tp * 2 + 1][lane] = a1;
    }
    __syncthreads();

    if (wid < 8) {
        const int tok = wid;
        float acc = Pp[0][tok][lane] + Pp[1][tok][lane]
                  + Pp[2][tok][lane] + Pp[3][tok][lane]
                  + b_out[d0 + lane];
        out[(t0 + tok) * Dm + d0 + lane] = acc;
    }
}

// ---------------------------------------------------------------------------
extern "C" void kernel_launch(void* const* d_in, const int* in_sizes, int n_in,
                              void* d_out, int out_size) {
    const float* inp   = (const float*)d_in[0];
    const float* w_in  = (const float*)d_in[1];
    const float* b_in  = (const float*)d_in[2];
    const float* ln_g  = (const float*)d_in[3];
    const float* ln_b  = (const float*)d_in[4];
    const float* w_out = (const float*)d_in[5];
    const float* b_out = (const float*)d_in[6];
    float* out = (float*)d_out;

    kA<<<dim3(16, 8), 512>>>(inp, w_in, b_in, ln_g, ln_b);
    kB<<<dim3(8, 8), 256>>>();
    kC<<<dim3(16, 8), 512>>>(w_out, b_out, out);
}

// round 5
// speedup vs baseline: 2.6138x; 1.1298x over previous
#include <cuda_runtime.h>
#include <math.h>

#define S    128
#define Dm   256
#define H    8
#define HD   32
#define KF   44          // feature order; also smem leading dim (44 = 4*11, odd m -> conflict-free)
#define BT   8           // tokens per block in proj phases

// 1/sqrt(24!)
#define RSF24 1.2695437e-12f

// Device scratch
__device__ float g_xln[H][S][HD];
__device__ float g_psi[H][S][KF];
__device__ float g_cat[S][Dm];

// ---- software grid barrier (all 128 CTAs co-resident: 1 CTA/SM, 128 <= 148 SMs)
__device__ unsigned g_bar;

__device__ __forceinline__ void grid_barrier() {
    __threadfence();                 // release: publish this thread's writes
    __syncthreads();
    if (threadIdx.x == 0) {
        unsigned t = atomicAdd(&g_bar, 1u);
        unsigned target = (t & ~127u) + 128u;   // end of this 128-ticket batch
        while ((int)(*(volatile unsigned*)&g_bar - target) < 0) __nanosleep(32);
    }
    __syncthreads();
    __threadfence();                 // acquire side
}

__device__ __forceinline__ float warpsum(float v) {
    #pragma unroll
    for (int o = 16; o > 0; o >>= 1) v += __shfl_xor_sync(0xffffffffu, v, o);
    return v;
}
__device__ __forceinline__ float warpmax(float v) {
    #pragma unroll
    for (int o = 16; o > 0; o >>= 1) v = fmaxf(v, __shfl_xor_sync(0xffffffffu, v, o));
    return v;
}

// 1/sqrt(k)
__device__ __constant__ float c_rsq[KF] = {
    1.0f,          1.0f,          0.70710678f,   0.57735027f,
    0.5f,          0.44721360f,   0.40824829f,   0.37796447f,
    0.35355339f,   0.33333333f,   0.31622777f,   0.30151134f,
    0.28867513f,   0.27735010f,   0.26726124f,   0.25819889f,
    0.25f,         0.24253563f,   0.23570226f,   0.22941573f,
    0.22360680f,   0.21821789f,   0.21320072f,   0.20851441f,
    0.20412415f,   0.2f,          0.19611614f,   0.19245009f,
    0.18898224f,   0.18569534f,   0.18257419f,   0.17960530f,
    0.17677670f,   0.17407766f,   0.17149859f,   0.16903085f,
    0.16666667f,   0.16439899f,   0.16222142f,   0.16012815f,
    0.15811388f,   0.15617376f,   0.15430335f,   0.15249857f
};

// Tree-merge reduction of 8 values across 32 lanes: 7 shuffles total.
// Afterwards lane group g=lane>>2 holds sum of v_{bitrev3(g)}; lanes with
// (lane&3)==0 scatter-store the 8 results into dst[kbase .. kbase+7].
__device__ __forceinline__ float feat_chunk8(float cur, float y, int kbase,
                                             float* dst, int lane, int nvalid) {
    float v0 = cur, v1, v2, v3, v4, v5, v6, v7;
    cur *= y * c_rsq[kbase + 1]; v1 = cur;
    cur *= y * c_rsq[kbase + 2]; v2 = cur;
    cur *= y * c_rsq[kbase + 3]; v3 = cur;
    if (nvalid > 4) {
        cur *= y * c_rsq[kbase + 4]; v4 = cur;
        cur *= y * c_rsq[kbase + 5]; v5 = cur;
        cur *= y * c_rsq[kbase + 6]; v6 = cur;
        cur *= y * c_rsq[kbase + 7]; v7 = cur;
    } else { v4 = v5 = v6 = v7 = 0.f; }

    const bool p16 = (lane & 16) == 0;
    float a0 = p16 ? v0 : v1, b0 = p16 ? v1 : v0; a0 += __shfl_xor_sync(0xffffffffu, b0, 16);
    float a1 = p16 ? v2 : v3, b1 = p16 ? v3 : v2; a1 += __shfl_xor_sync(0xffffffffu, b1, 16);
    float a2 = p16 ? v4 : v5, b2 = p16 ? v5 : v4; a2 += __shfl_xor_sync(0xffffffffu, b2, 16);
    float a3 = p16 ? v6 : v7, b3 = p16 ? v7 : v6; a3 += __shfl_xor_sync(0xffffffffu, b3, 16);
    const bool p8 = (lane & 8) == 0;
    float c0 = p8 ? a0 : a1, d0 = p8 ? a1 : a0; c0 += __shfl_xor_sync(0xffffffffu, d0, 8);
    float c1 = p8 ? a2 : a3, d1 = p8 ? a3 : a2; c1 += __shfl_xor_sync(0xffffffffu, d1, 8);
    const bool p4 = (lane & 4) == 0;
    float e0 = p4 ? c0 : c1, f0 = p4 ? c1 : c0; e0 += __shfl_xor_sync(0xffffffffu, f0, 4);
    e0 += __shfl_xor_sync(0xffffffffu, e0, 2);
    e0 += __shfl_xor_sync(0xffffffffu, e0, 1);

    if ((lane & 3) == 0) {
        int g = lane >> 2;
        int j = ((g & 1) << 2) | (g & 2) | (g >> 2);   // bitrev3
        if (j < nvalid) dst[kbase + j] = e0;
    }
    return cur;
}

// ---- shared memory union (phase 1/3 vs phase 2), 47,104 B max ----
struct SmA { float As[BT][260]; float Bs[HD][260]; float Pp[4][BT][HD]; };
struct SmB { float Ps[S][KF]; float Xs[S][HD]; float Sc[16][S]; };
#define SMEM_BYTES (sizeof(SmB) > sizeof(SmA) ? sizeof(SmB) : sizeof(SmA))

// ---------------------------------------------------------------------------
// Single fused kernel: phase1 proj+LN+features | barrier | phase2 attention
// | barrier | phase3 out-proj. grid 128 x 512.
// ---------------------------------------------------------------------------
__global__ void __launch_bounds__(512, 1) kFused(const float* __restrict__ inp,
                                                 const float* __restrict__ w_in,
                                                 const float* __restrict__ b_in,
                                                 const float* __restrict__ ln_g,
                                                 const float* __restrict__ ln_b,
                                                 const float* __restrict__ w_out,
                                                 const float* __restrict__ b_out,
                                                 float* __restrict__ out) {
    __shared__ __align__(16) char smraw[SMEM_BYTES];
    SmA& A  = *reinterpret_cast<SmA*>(smraw);
    SmB& Bm = *reinterpret_cast<SmB*>(smraw);

    const int b    = blockIdx.x;
    const int tid  = threadIdx.x;
    const int lane = tid & 31, wid = tid >> 5;    // 16 warps

    // ===================== Phase 1: proj + LN + features =====================
    {
        const int t0 = (b & 15) * BT;
        const int h  = b >> 4;

        for (int i = tid; i < BT * 64; i += 512) {
            int r = i >> 6, c4 = i & 63;
            *(float4*)&A.As[r][c4 * 4] = *(const float4*)&inp[(t0 + r) * Dm + c4 * 4];
        }
        for (int i = tid; i < HD * 64; i += 512) {
            int r = i >> 6, c4 = i & 63;
            *(float4*)&A.Bs[r][c4 * 4] = *(const float4*)&w_in[(h * HD + r) * Dm + c4 * 4];
        }
        __syncthreads();

        {   // GEMM: kq = K-quarter, tp = token pair
            const int kq = wid >> 2, tp = wid & 3;
            float a0 = 0.f, a1 = 0.f;
            #pragma unroll
            for (int k4 = kq * 16; k4 < kq * 16 + 16; ++k4) {
                float4 bv = *(float4*)&A.Bs[lane][k4 * 4];
                float4 x0 = *(float4*)&A.As[tp * 2 + 0][k4 * 4];
                float4 x1 = *(float4*)&A.As[tp * 2 + 1][k4 * 4];
                a0 = fmaf(x0.x, bv.x, a0); a0 = fmaf(x0.y, bv.y, a0);
                a0 = fmaf(x0.z, bv.z, a0); a0 = fmaf(x0.w, bv.w, a0);
                a1 = fmaf(x1.x, bv.x, a1); a1 = fmaf(x1.y, bv.y, a1);
                a1 = fmaf(x1.z, bv.z, a1); a1 = fmaf(x1.w, bv.w, a1);
            }
            A.Pp[kq][tp * 2 + 0][lane] = a0;
            A.Pp[kq][tp * 2 + 1][lane] = a1;
        }
        __syncthreads();

        const int tok = wid & 7;
        float acc = A.Pp[0][tok][lane] + A.Pp[1][tok][lane]
                  + A.Pp[2][tok][lane] + A.Pp[3][tok][lane]
                  + b_in[h * HD + lane];

        const float mu  = warpsum(acc) * (1.0f / 32.0f);
        const float d   = acc - mu;
        const float var = warpsum(d * d) * (1.0f / 32.0f);
        const float y   = d * rsqrtf(var + 1e-5f) * ln_g[lane] + ln_b[lane];
        const int   tg  = t0 + tok;
        if (wid < 8) g_xln[h][tg][lane] = y;

        float* dst = &g_psi[h][tg][0];
        const float t0e = __expf(-0.5f * y * y);
        if (wid < 8) {                      // k in [0,24)
            float cur = t0e;
            cur = feat_chunk8(cur, y, 0, dst, lane, 8);
            cur *= y * c_rsq[8];
            cur = feat_chunk8(cur, y, 8, dst, lane, 8);
            cur *= y * c_rsq[16];
            feat_chunk8(cur, y, 16, dst, lane, 8);
        } else {                            // k in [24,44)
            const float y2 = y * y, y4 = y2 * y2, y8 = y4 * y4, y16 = y8 * y8;
            float cur = t0e * (y16 * y8) * RSF24;   // k = 24
            cur = feat_chunk8(cur, y, 24, dst, lane, 8);
            cur *= y * c_rsq[32];
            cur = feat_chunk8(cur, y, 32, dst, lane, 8);
            cur *= y * c_rsq[40];
            feat_chunk8(cur, y, 40, dst, lane, 4);
        }
    }

    grid_barrier();

    // ===================== Phase 2: scores + softmax + AV ====================
    if (b < 64) {
        const int s0 = (b & 7) * 16;
        const int h  = b >> 3;

        const float* psi = &g_psi[h][0][0];
        for (int i = tid; i < S * (KF / 4); i += 512) {
            int r = i / (KF / 4), c4 = i - r * (KF / 4);
            *(float4*)&Bm.Ps[r][c4 * 4] = *(const float4*)&psi[r * KF + c4 * 4];
        }
        const float* xl = &g_xln[h][0][0];
        for (int i = tid; i < S * (HD / 4); i += 512) {
            int r = i >> 3, c4 = i & 7;
            *(float4*)&Bm.Xs[r][c4 * 4] = *(const float4*)&xl[r * HD + c4 * 4];
        }
        __syncthreads();

        // one row per warp: scores + softmax fully in registers
        const int row = s0 + wid;
        float acc[4] = {0.f, 0.f, 0.f, 0.f};
        #pragma unroll
        for (int kg = 0; kg < KF / 4; ++kg) {
            float4 rs = *(float4*)&Bm.Ps[row][kg * 4];       // broadcast
            #pragma unroll
            for (int tj = 0; tj < 4; ++tj) {
                float4 rt = *(float4*)&Bm.Ps[lane + 32 * tj][kg * 4];  // stride 44: conflict-free
                acc[tj] = fmaf(rs.x, rt.x, acc[tj]);
                acc[tj] = fmaf(rs.y, rt.y, acc[tj]);
                acc[tj] = fmaf(rs.z, rt.z, acc[tj]);
                acc[tj] = fmaf(rs.w, rt.w, acc[tj]);
            }
        }
        #pragma unroll
        for (int tj = 0; tj < 4; ++tj) acc[tj] *= (1.0f / 32.0f);

        float m = warpmax(fmaxf(fmaxf(acc[0], acc[1]), fmaxf(acc[2], acc[3])));
        float sum = 0.f;
        #pragma unroll
        for (int tj = 0; tj < 4; ++tj) { acc[tj] = __expf(acc[tj] - m); sum += acc[tj]; }
        sum = warpsum(sum);
        const float inv = 1.0f / sum;
        #pragma unroll
        for (int tj = 0; tj < 4; ++tj) Bm.Sc[wid][lane + 32 * tj] = acc[tj] * inv;
        __syncwarp();

        // AV: out[row][e=lane]
        float o = 0.f;
        #pragma unroll 8
        for (int t4 = 0; t4 < S / 4; ++t4) {
            float4 p4 = *(float4*)&Bm.Sc[wid][t4 * 4];        // broadcast
            o = fmaf(p4.x, Bm.Xs[t4 * 4 + 0][lane], o);
            o = fmaf(p4.y, Bm.Xs[t4 * 4 + 1][lane], o);
            o = fmaf(p4.z, Bm.Xs[t4 * 4 + 2][lane], o);
            o = fmaf(p4.w, Bm.Xs[t4 * 4 + 3][lane], o);
        }
        g_cat[row][h * HD + lane] = o;
    }

    grid_barrier();

    // ===================== Phase 3: out-projection ===========================
    {
        const int t0 = (b & 15) * BT;
        const int d0 = (b >> 4) * 32;

        for (int i = tid; i < BT * 64; i += 512) {
            int r = i >> 6, c4 = i & 63;
            *(float4*)&A.As[r][c4 * 4] = *(const float4*)&g_cat[t0 + r][c4 * 4];
        }
        for (int i = tid; i < HD * 64; i += 512) {
            int r = i >> 6, c4 = i & 63;
            *(float4*)&A.Bs[r][c4 * 4] = *(const float4*)&w_out[(d0 + r) * Dm + c4 * 4];
        }
        __syncthreads();

        {
            const int kq = wid >> 2, tp = wid & 3;
            float a0 = 0.f, a1 = 0.f;
            #pragma unroll
            for (int k4 = kq * 16; k4 < kq * 16 + 16; ++k4) {
                float4 bv = *(float4*)&A.Bs[lane][k4 * 4];
                float4 x0 = *(float4*)&A.As[tp * 2 + 0][k4 * 4];
                float4 x1 = *(float4*)&A.As[tp * 2 + 1][k4 * 4];
                a0 = fmaf(x0.x, bv.x, a0); a0 = fmaf(x0.y, bv.y, a0);
                a0 = fmaf(x0.z, bv.z, a0); a0 = fmaf(x0.w, bv.w, a0);
                a1 = fmaf(x1.x, bv.x, a1); a1 = fmaf(x1.y, bv.y, a1);
                a1 = fmaf(x1.z, bv.z, a1); a1 = fmaf(x1.w, bv.w, a1);
            }
            A.Pp[kq][tp * 2 + 0][lane] = a0;
            A.Pp[kq][tp * 2 + 1][lane] = a1;
        }
        __syncthreads();

        if (wid < 8) {
            const int tok = wid;
            float acc = A.Pp[0][tok][lane] + A.Pp[1][tok][lane]
                      + A.Pp[2][tok][lane] + A.Pp[3][tok][lane]
                      + b_out[d0 + lane];
            out[(t0 + tok) * Dm + d0 + lane] = acc;
        }
    }
}

// ---------------------------------------------------------------------------
extern "C" void kernel_launch(void* const* d_in, const int* in_sizes, int n_in,
                              void* d_out, int out_size) {
    const float* inp   = (const float*)d_in[0];
    const float* w_in  = (const float*)d_in[1];
    const float* b_in  = (const float*)d_in[2];
    const float* ln_g  = (const float*)d_in[3];
    const float* ln_b  = (const float*)d_in[4];
    const float* w_out = (const float*)d_in[5];
    const float* b_out = (const float*)d_in[6];
    float* out = (float*)d_out;

    kFused<<<128, 512>>>(inp, w_in, b_in, ln_g, ln_b, w_out, b_out, out);
}

// round 6
// speedup vs baseline: 3.1547x; 1.2070x over previous
#include <cuda_runtime.h>
#include <math.h>

#define S    128
#define Dm   256
#define H    8
#define HD   32
#define KF   44          // feature order; smem leading dim (44: odd multiple of 4 -> conflict-free f4)
#define BT   8           // tokens per block in proj phases

// 1/sqrt(24!)
#define RSF24 1.2695437e-12f

// Device scratch
__device__ float g_xln[H][S][HD];
__device__ float g_psi[H][S][KF];
__device__ float g_cat[S][Dm];

// ---- fence-free software grid barrier (all 128 CTAs co-resident: 1 CTA/SM) ----
// Only thread 0 touches memory ordering: bar.sync gives intra-CTA happens-before
// into the release-atomic; ld.acquire + bar.sync propagates it back out.
__device__ unsigned g_bar;

__device__ __forceinline__ void grid_barrier() {
    __syncthreads();
    if (threadIdx.x == 0) {
        unsigned t;
        asm volatile("atom.add.release.gpu.u32 %0, [%1], 1;"
                     : "=r"(t) : "l"(&g_bar) : "memory");
        const unsigned target = (t & ~127u) + 128u;   // end of this 128-ticket batch
        unsigned cur;
        do {
            asm volatile("ld.acquire.gpu.u32 %0, [%1];"
                         : "=r"(cur) : "l"(&g_bar) : "memory");
        } while ((int)(cur - target) < 0);
    }
    __syncthreads();
}

__device__ __forceinline__ float warpsum(float v) {
    #pragma unroll
    for (int o = 16; o > 0; o >>= 1) v += __shfl_xor_sync(0xffffffffu, v, o);
    return v;
}
__device__ __forceinline__ float warpmax(float v) {
    #pragma unroll
    for (int o = 16; o > 0; o >>= 1) v = fmaxf(v, __shfl_xor_sync(0xffffffffu, v, o));
    return v;
}

// 1/sqrt(k)
__device__ __constant__ float c_rsq[KF] = {
    1.0f,          1.0f,          0.70710678f,   0.57735027f,
    0.5f,          0.44721360f,   0.40824829f,   0.37796447f,
    0.35355339f,   0.33333333f,   0.31622777f,   0.30151134f,
    0.28867513f,   0.27735010f,   0.26726124f,   0.25819889f,
    0.25f,         0.24253563f,   0.23570226f,   0.22941573f,
    0.22360680f,   0.21821789f,   0.21320072f,   0.20851441f,
    0.20412415f,   0.2f,          0.19611614f,   0.19245009f,
    0.18898224f,   0.18569534f,   0.18257419f,   0.17960530f,
    0.17677670f,   0.17407766f,   0.17149859f,   0.16903085f,
    0.16666667f,   0.16439899f,   0.16222142f,   0.16012815f,
    0.15811388f,   0.15617376f,   0.15430335f,   0.15249857f
};

// Tree-merge reduction of 8 values across 32 lanes: 7 shuffles total.
__device__ __forceinline__ float feat_chunk8(float cur, float y, int kbase,
                                             float* dst, int lane, int nvalid) {
    float v0 = cur, v1, v2, v3, v4, v5, v6, v7;
    cur *= y * c_rsq[kbase + 1]; v1 = cur;
    cur *= y * c_rsq[kbase + 2]; v2 = cur;
    cur *= y * c_rsq[kbase + 3]; v3 = cur;
    if (nvalid > 4) {
        cur *= y * c_rsq[kbase + 4]; v4 = cur;
        cur *= y * c_rsq[kbase + 5]; v5 = cur;
        cur *= y * c_rsq[kbase + 6]; v6 = cur;
        cur *= y * c_rsq[kbase + 7]; v7 = cur;
    } else { v4 = v5 = v6 = v7 = 0.f; }

    const bool p16 = (lane & 16) == 0;
    float a0 = p16 ? v0 : v1, b0 = p16 ? v1 : v0; a0 += __shfl_xor_sync(0xffffffffu, b0, 16);
    float a1 = p16 ? v2 : v3, b1 = p16 ? v3 : v2; a1 += __shfl_xor_sync(0xffffffffu, b1, 16);
    float a2 = p16 ? v4 : v5, b2 = p16 ? v5 : v4; a2 += __shfl_xor_sync(0xffffffffu, b2, 16);
    float a3 = p16 ? v6 : v7, b3 = p16 ? v7 : v6; a3 += __shfl_xor_sync(0xffffffffu, b3, 16);
    const bool p8 = (lane & 8) == 0;
    float c0 = p8 ? a0 : a1, d0 = p8 ? a1 : a0; c0 += __shfl_xor_sync(0xffffffffu, d0, 8);
    float c1 = p8 ? a2 : a3, d1 = p8 ? a3 : a2; c1 += __shfl_xor_sync(0xffffffffu, d1, 8);
    const bool p4 = (lane & 4) == 0;
    float e0 = p4 ? c0 : c1, f0 = p4 ? c1 : c0; e0 += __shfl_xor_sync(0xffffffffu, f0, 4);
    e0 += __shfl_xor_sync(0xffffffffu, e0, 2);
    e0 += __shfl_xor_sync(0xffffffffu, e0, 1);

    if ((lane & 3) == 0) {
        int g = lane >> 2;
        int j = ((g & 1) << 2) | (g & 2) | (g >> 2);   // bitrev3
        if (j < nvalid) dst[kbase + j] = e0;
    }
    return cur;
}

// ---- shared memory union (phase 1/3 vs phase 2) ----
struct SmA { float As[BT][260]; float Bs[HD][260]; float Pp[4][BT][HD]; };   // 45,696 B
struct SmB { float Ps[S][KF]; float Xs[S][HD]; float Sc[8][S]; };            // 43,008 B
#define SMEM_BYTES (sizeof(SmB) > sizeof(SmA) ? sizeof(SmB) : sizeof(SmA))

// ---------------------------------------------------------------------------
// Single fused kernel. grid 128 x 512.
// ---------------------------------------------------------------------------
__global__ void __launch_bounds__(512, 1) kFused(const float* __restrict__ inp,
                                                 const float* __restrict__ w_in,
                                                 const float* __restrict__ b_in,
                                                 const float* __restrict__ ln_g,
                                                 const float* __restrict__ ln_b,
                                                 const float* __restrict__ w_out,
                                                 const float* __restrict__ b_out,
                                                 float* __restrict__ out) {
    __shared__ __align__(16) char smraw[SMEM_BYTES];
    SmA& A  = *reinterpret_cast<SmA*>(smraw);
    SmB& Bm = *reinterpret_cast<SmB*>(smraw);

    const int b    = blockIdx.x;
    const int tid  = threadIdx.x;
    const int lane = tid & 31, wid = tid >> 5;    // 16 warps

    // ===================== Phase 1: proj + LN + features =====================
    {
        const int t0 = (b & 15) * BT;
        const int h  = b >> 4;

        for (int i = tid; i < BT * 64; i += 512) {
            int r = i >> 6, c4 = i & 63;
            *(float4*)&A.As[r][c4 * 4] = *(const float4*)&inp[(t0 + r) * Dm + c4 * 4];
        }
        for (int i = tid; i < HD * 64; i += 512) {
            int r = i >> 6, c4 = i & 63;
            *(float4*)&A.Bs[r][c4 * 4] = *(const float4*)&w_in[(h * HD + r) * Dm + c4 * 4];
        }

        // L2-prefetch this CTA's phase-3 weight tile (32 rows of w_out, 256 lines)
        {
            const int d0 = (b >> 4) * 32;
            if (tid < 256) {
                const float* p = w_out + d0 * Dm + tid * 32;
                asm volatile("prefetch.global.L2 [%0];" :: "l"(p));
            }
        }
        __syncthreads();

        {   // GEMM: kq = K-quarter, tp = token pair
            const int kq = wid >> 2, tp = wid & 3;
            float a0 = 0.f, a1 = 0.f;
            #pragma unroll
            for (int k4 = kq * 16; k4 < kq * 16 + 16; ++k4) {
                float4 bv = *(float4*)&A.Bs[lane][k4 * 4];
                float4 x0 = *(float4*)&A.As[tp * 2 + 0][k4 * 4];
                float4 x1 = *(float4*)&A.As[tp * 2 + 1][k4 * 4];
                a0 = fmaf(x0.x, bv.x, a0); a0 = fmaf(x0.y, bv.y, a0);
                a0 = fmaf(x0.z, bv.z, a0); a0 = fmaf(x0.w, bv.w, a0);
                a1 = fmaf(x1.x, bv.x, a1); a1 = fmaf(x1.y, bv.y, a1);
                a1 = fmaf(x1.z, bv.z, a1); a1 = fmaf(x1.w, bv.w, a1);
            }
            A.Pp[kq][tp * 2 + 0][lane] = a0;
            A.Pp[kq][tp * 2 + 1][lane] = a1;
        }
        __syncthreads();

        const int tok = wid & 7;
        float acc = A.Pp[0][tok][lane] + A.Pp[1][tok][lane]
                  + A.Pp[2][tok][lane] + A.Pp[3][tok][lane]
                  + b_in[h * HD + lane];

        const float mu  = warpsum(acc) * (1.0f / 32.0f);
        const float d   = acc - mu;
        const float var = warpsum(d * d) * (1.0f / 32.0f);
        const float y   = d * rsqrtf(var + 1e-5f) * ln_g[lane] + ln_b[lane];
        const int   tg  = t0 + tok;
        if (wid < 8) g_xln[h][tg][lane] = y;

        float* dst = &g_psi[h][tg][0];
        const float t0e = __expf(-0.5f * y * y);
        if (wid < 8) {                      // k in [0,24)
            float cur = t0e;
            cur = feat_chunk8(cur, y, 0, dst, lane, 8);
            cur *= y * c_rsq[8];
            cur = feat_chunk8(cur, y, 8, dst, lane, 8);
            cur *= y * c_rsq[16];
            feat_chunk8(cur, y, 16, dst, lane, 8);
        } else {                            // k in [24,44)
            const float y2 = y * y, y4 = y2 * y2, y8 = y4 * y4, y16 = y8 * y8;
            float cur = t0e * (y16 * y8) * RSF24;   // k = 24
            cur = feat_chunk8(cur, y, 24, dst, lane, 8);
            cur *= y * c_rsq[32];
            cur = feat_chunk8(cur, y, 32, dst, lane, 8);
            cur *= y * c_rsq[40];
            feat_chunk8(cur, y, 40, dst, lane, 4);
        }
    }

    grid_barrier();

    // ========== Phase 2: scores + softmax + AV (all 128 CTAs, 8 rows each) ==========
    {
        const int s0 = (b & 15) * 8;
        const int h  = b >> 4;

        const float* psi = &g_psi[h][0][0];
        for (int i = tid; i < S * (KF / 4); i += 512) {
            int r = i / (KF / 4), c4 = i - r * (KF / 4);
            *(float4*)&Bm.Ps[r][c4 * 4] = *(const float4*)&psi[r * KF + c4 * 4];
        }
        const float* xl = &g_xln[h][0][0];
        for (int i = tid; i < S * (HD / 4); i += 512) {
            int r = i >> 3, c4 = i & 7;
            *(float4*)&Bm.Xs[r][c4 * 4] = *(const float4*)&xl[r * HD + c4 * 4];
        }
        __syncthreads();

        if (wid < 8) {
            // one row per warp: scores + softmax fully in registers
            const int row = s0 + wid;
            float acc[4] = {0.f, 0.f, 0.f, 0.f};
            #pragma unroll
            for (int kg = 0; kg < KF / 4; ++kg) {
                float4 rs = *(float4*)&Bm.Ps[row][kg * 4];       // broadcast
                #pragma unroll
                for (int tj = 0; tj < 4; ++tj) {
                    float4 rt = *(float4*)&Bm.Ps[lane + 32 * tj][kg * 4];  // stride 44: conflict-free
                    acc[tj] = fmaf(rs.x, rt.x, acc[tj]);
                    acc[tj] = fmaf(rs.y, rt.y, acc[tj]);
                    acc[tj] = fmaf(rs.z, rt.z, acc[tj]);
                    acc[tj] = fmaf(rs.w, rt.w, acc[tj]);
                }
            }
            #pragma unroll
            for (int tj = 0; tj < 4; ++tj) acc[tj] *= (1.0f / 32.0f);

            float m = warpmax(fmaxf(fmaxf(acc[0], acc[1]), fmaxf(acc[2], acc[3])));
            float sum = 0.f;
            #pragma unroll
            for (int tj = 0; tj < 4; ++tj) { acc[tj] = __expf(acc[tj] - m); sum += acc[tj]; }
            sum = warpsum(sum);
            const float inv = 1.0f / sum;
            #pragma unroll
            for (int tj = 0; tj < 4; ++tj) Bm.Sc[wid][lane + 32 * tj] = acc[tj] * inv;
            __syncwarp();

            // AV: out[row][e=lane]
            float o = 0.f;
            #pragma unroll 8
            for (int t4 = 0; t4 < S / 4; ++t4) {
                float4 p4 = *(float4*)&Bm.Sc[wid][t4 * 4];        // broadcast
                o = fmaf(p4.x, Bm.Xs[t4 * 4 + 0][lane], o);
                o = fmaf(p4.y, Bm.Xs[t4 * 4 + 1][lane], o);
                o = fmaf(p4.z, Bm.Xs[t4 * 4 + 2][lane], o);
                o = fmaf(p4.w, Bm.Xs[t4 * 4 + 3][lane], o);
            }
            g_cat[row][h * HD + lane] = o;
        }
    }

    grid_barrier();

    // ===================== Phase 3: out-projection ===========================
    {
        const int t0 = (b & 15) * BT;
        const int d0 = (b >> 4) * 32;

        for (int i = tid; i < BT * 64; i += 512) {
            int r = i >> 6, c4 = i & 63;
            *(float4*)&A.As[r][c4 * 4] = *(const float4*)&g_cat[t0 + r][c4 * 4];
        }
        for (int i = tid; i < HD * 64; i += 512) {
            int r = i >> 6, c4 = i & 63;
            *(float4*)&A.Bs[r][c4 * 4] = *(const float4*)&w_out[(d0 + r) * Dm + c4 * 4];
        }
        __syncthreads();

        {
            const int kq = wid >> 2, tp = wid & 3;
            float a0 = 0.f, a1 = 0.f;
            #pragma unroll
            for (int k4 = kq * 16; k4 < kq * 16 + 16; ++k4) {
                float4 bv = *(float4*)&A.Bs[lane][k4 * 4];
                float4 x0 = *(float4*)&A.As[tp * 2 + 0][k4 * 4];
                float4 x1 = *(float4*)&A.As[tp * 2 + 1][k4 * 4];
                a0 = fmaf(x0.x, bv.x, a0); a0 = fmaf(x0.y, bv.y, a0);
                a0 = fmaf(x0.z, bv.z, a0); a0 = fmaf(x0.w, bv.w, a0);
                a1 = fmaf(x1.x, bv.x, a1); a1 = fmaf(x1.y, bv.y, a1);
                a1 = fmaf(x1.z, bv.z, a1); a1 = fmaf(x1.w, bv.w, a1);
            }
            A.Pp[kq][tp * 2 + 0][lane] = a0;
            A.Pp[kq][tp * 2 + 1][lane] = a1;
        }
        __syncthreads();

        if (wid < 8) {
            const int tok = wid;
            float acc = A.Pp[0][tok][lane] + A.Pp[1][tok][lane]
                      + A.Pp[2][tok][lane] + A.Pp[3][tok][lane]
                      + b_out[d0 + lane];
            out[(t0 + tok) * Dm + d0 + lane] = acc;
        }
    }
}

// ---------------------------------------------------------------------------
extern "C" void kernel_launch(void* const* d_in, const int* in_sizes, int n_in,
                              void* d_out, int out_size) {
    const float* inp   = (const float*)d_in[0];
    const float* w_in  = (const float*)d_in[1];
    const float* b_in  = (const float*)d_in[2];
    const float* ln_g  = (const float*)d_in[3];
    const float* ln_b  = (const float*)d_in[4];
    const float* w_out = (const float*)d_in[5];
    const float* b_out = (const float*)d_in[6];
    float* out = (float*)d_out;

    kFused<<<128, 512>>>(inp, w_in, b_in, ln_g, ln_b, w_out, b_out, out);
}

// round 7
// speedup vs baseline: 3.1793x; 1.0078x over previous
#include <cuda_runtime.h>
#include <math.h>

#define S    128
#define Dm   256
#define H    8
#define HD   32
#define KF   48          // feature order (48 = 6 chunks of 8, 12 float4 groups)
#define KP2  52          // smem leading dim for psi in phase 2 (52: conflict-free f4 stride)
#define BT   8           // tokens per block in proj phases

// 1/sqrt((8m)!)
#define RSF8  4.980119e-3f
#define RSF16 2.186202e-7f
#define RSF24 1.269544e-12f
#define RSF32 1.949459e-18f
#define RSF40 1.107076e-24f

// Device scratch
__device__ float g_xln[H][S][HD];
__device__ float g_psi[H][S][KF];
__device__ float g_cat[S][Dm];

// Producer/consumer counters, one 128B line each (LTS atomics serialize per line).
__device__ unsigned g_cnt1[H][32];    // per head: 16 producers (phase1 -> phase2)
__device__ unsigned g_cnt2[16][32];   // per token group: 8 producers (phase2 -> phase3)

__device__ __forceinline__ unsigned ld_relaxed(const unsigned* p) {
    unsigned v;
    asm volatile("ld.relaxed.gpu.u32 %0, [%1];" : "=r"(v) : "l"(p) : "memory");
    return v;
}
__device__ __forceinline__ void release_add(unsigned* p) {
    unsigned t;
    asm volatile("atom.add.release.gpu.u32 %0, [%1], 1;" : "=r"(t) : "l"(p) : "memory");
}
__device__ __forceinline__ void acquire_wait(const unsigned* p, unsigned target) {
    unsigned cur;
    do {
        asm volatile("ld.acquire.gpu.u32 %0, [%1];" : "=r"(cur) : "l"(p) : "memory");
    } while ((int)(cur - target) < 0);
}

__device__ __forceinline__ float warpmax(float v) {
    #pragma unroll
    for (int o = 16; o > 0; o >>= 1) v = fmaxf(v, __shfl_xor_sync(0xffffffffu, v, o));
    return v;
}
__device__ __forceinline__ float warpsum(float v) {
    #pragma unroll
    for (int o = 16; o > 0; o >>= 1) v += __shfl_xor_sync(0xffffffffu, v, o);
    return v;
}

// 1/sqrt(k), k = 0..47
__device__ __constant__ float c_rsq[KF] = {
    1.0f,          1.0f,          0.70710678f,   0.57735027f,
    0.5f,          0.44721360f,   0.40824829f,   0.37796447f,
    0.35355339f,   0.33333333f,   0.31622777f,   0.30151134f,
    0.28867513f,   0.27735010f,   0.26726124f,   0.25819889f,
    0.25f,         0.24253563f,   0.23570226f,   0.22941573f,
    0.22360680f,   0.21821789f,   0.21320072f,   0.20851441f,
    0.20412415f,   0.2f,          0.19611614f,   0.19245009f,
    0.18898224f,   0.18569534f,   0.18257419f,   0.17960530f,
    0.17677670f,   0.17407766f,   0.17149859f,   0.16903085f,
    0.16666667f,   0.16439899f,   0.16222142f,   0.16012815f,
    0.15811388f,   0.15617376f,   0.15430335f,   0.15249857f,
    0.15075567f,   0.14907120f,   0.14744196f,   0.14586499f
};

// 8 independent-start series values from 'start' at k = kbase.
__device__ __forceinline__ void feat8_vals(float start, float y, int kbase, float* v) {
    v[0] = start;
    #pragma unroll
    for (int j = 1; j < 8; ++j) v[j] = v[j - 1] * y * c_rsq[kbase + j];
}

// Tree-merge 8 values across 32 lanes (7 shuffles), scatter-store by lane groups.
__device__ __forceinline__ void feat8_reduce_store(const float* v, float* dst,
                                                   int kbase, int lane) {
    const bool p16 = (lane & 16) == 0;
    float a0 = p16 ? v[0] : v[1], b0 = p16 ? v[1] : v[0]; a0 += __shfl_xor_sync(0xffffffffu, b0, 16);
    float a1 = p16 ? v[2] : v[3], b1 = p16 ? v[3] : v[2]; a1 += __shfl_xor_sync(0xffffffffu, b1, 16);
    float a2 = p16 ? v[4] : v[5], b2 = p16 ? v[5] : v[4]; a2 += __shfl_xor_sync(0xffffffffu, b2, 16);
    float a3 = p16 ? v[6] : v[7], b3 = p16 ? v[7] : v[6]; a3 += __shfl_xor_sync(0xffffffffu, b3, 16);
    const bool p8 = (lane & 8) == 0;
    float c0 = p8 ? a0 : a1, d0 = p8 ? a1 : a0; c0 += __shfl_xor_sync(0xffffffffu, d0, 8);
    float c1 = p8 ? a2 : a3, d1 = p8 ? a3 : a2; c1 += __shfl_xor_sync(0xffffffffu, d1, 8);
    const bool p4 = (lane & 4) == 0;
    float e0 = p4 ? c0 : c1, f0 = p4 ? c1 : c0; e0 += __shfl_xor_sync(0xffffffffu, f0, 4);
    e0 += __shfl_xor_sync(0xffffffffu, e0, 2);
    e0 += __shfl_xor_sync(0xffffffffu, e0, 1);
    if ((lane & 3) == 0) {
        int g = lane >> 2;
        int j = ((g & 1) << 2) | (g & 2) | (g >> 2);   // bitrev3
        dst[kbase + j] = e0;
    }
}

// ---- shared memory union (phase 1/3 vs phase 2) ----
struct SmA { float As[BT][260]; float Bs[HD][260]; float Pp[4][BT][HD]; };          // 45,696 B
struct SmB { float Ps[S][KP2]; float Xs[S][HD]; float Sc[8][S]; float Pav[2][8][HD]; }; // 49,152 B
#define SMEM_BYTES (sizeof(SmB) > sizeof(SmA) ? sizeof(SmB) : sizeof(SmA))

// ---------------------------------------------------------------------------
// Single fused kernel. grid 128 x 512. CTA b: token group g = b&15, head/dblock h = b>>4.
// ---------------------------------------------------------------------------
__global__ void __launch_bounds__(512, 1) kFused(const float* __restrict__ inp,
                                                 const float* __restrict__ w_in,
                                                 const float* __restrict__ b_in,
                                                 const float* __restrict__ ln_g,
                                                 const float* __restrict__ ln_b,
                                                 const float* __restrict__ w_out,
                                                 const float* __restrict__ b_out,
                                                 float* __restrict__ out) {
    __shared__ __align__(16) char smraw[SMEM_BYTES];
    SmA& A  = *reinterpret_cast<SmA*>(smraw);
    SmB& Bm = *reinterpret_cast<SmB*>(smraw);

    const int b    = blockIdx.x;
    const int tid  = threadIdx.x;
    const int lane = tid & 31, wid = tid >> 5;    // 16 warps
    const int grp  = b & 15;                       // token group
    const int h    = b >> 4;                       // head / d-block index

    // Snapshot counters at entry (this CTA is itself a pending producer of both
    // counters it consumes, so snapshot < target batch is guaranteed).
    unsigned tgt1 = 0, tgt2 = 0;
    if (tid == 0) {
        tgt1 = (ld_relaxed(&g_cnt1[h][0])   & ~15u) + 16u;
        tgt2 = (ld_relaxed(&g_cnt2[grp][0]) & ~7u)  + 8u;
    }

    // ===================== Phase 1: proj + LN + features =====================
    {
        const int t0 = grp * BT;

        for (int i = tid; i < BT * 64; i += 512) {
            int r = i >> 6, c4 = i & 63;
            *(float4*)&A.As[r][c4 * 4] = *(const float4*)&inp[(t0 + r) * Dm + c4 * 4];
        }
        for (int i = tid; i < HD * 64; i += 512) {
            int r = i >> 6, c4 = i & 63;
            *(float4*)&A.Bs[r][c4 * 4] = *(const float4*)&w_in[(h * HD + r) * Dm + c4 * 4];
        }
        // L2-prefetch this CTA's phase-3 weight tile
        if (tid < 256) {
            const float* p = w_out + (h * 32) * Dm + tid * 32;
            asm volatile("prefetch.global.L2 [%0];" :: "l"(p));
        }
        __syncthreads();

        {   // GEMM: kq = K-quarter, tp = token pair
            const int kq = wid >> 2, tp = wid & 3;
            float a0 = 0.f, a1 = 0.f;
            #pragma unroll
            for (int k4 = kq * 16; k4 < kq * 16 + 16; ++k4) {
                float4 bv = *(float4*)&A.Bs[lane][k4 * 4];
                float4 x0 = *(float4*)&A.As[tp * 2 + 0][k4 * 4];
                float4 x1 = *(float4*)&A.As[tp * 2 + 1][k4 * 4];
                a0 = fmaf(x0.x, bv.x, a0); a0 = fmaf(x0.y, bv.y, a0);
                a0 = fmaf(x0.z, bv.z, a0); a0 = fmaf(x0.w, bv.w, a0);
                a1 = fmaf(x1.x, bv.x, a1); a1 = fmaf(x1.y, bv.y, a1);
                a1 = fmaf(x1.z, bv.z, a1); a1 = fmaf(x1.w, bv.w, a1);
            }
            A.Pp[kq][tp * 2 + 0][lane] = a0;
            A.Pp[kq][tp * 2 + 1][lane] = a1;
        }
        __syncthreads();

        const int tok = wid & 7;
        float acc = A.Pp[0][tok][lane] + A.Pp[1][tok][lane]
                  + A.Pp[2][tok][lane] + A.Pp[3][tok][lane]
                  + b_in[h * HD + lane];

        // LayerNorm: sum & sumsq in one interleaved butterfly
        float s1 = acc, s2 = acc * acc;
        #pragma unroll
        for (int o = 16; o > 0; o >>= 1) {
            s1 += __shfl_xor_sync(0xffffffffu, s1, o);
            s2 += __shfl_xor_sync(0xffffffffu, s2, o);
        }
        const float mu  = s1 * (1.0f / 32.0f);
        const float var = fmaf(-mu, mu, s2 * (1.0f / 32.0f));
        const float y   = (acc - mu) * rsqrtf(var + 1e-5f) * ln_g[lane] + ln_b[lane];
        const int   tg  = t0 + tok;
        if (wid < 8) g_xln[h][tg][lane] = y;

        // Features: 3 independent 8-chunks per warp-half
        float* dst = &g_psi[h][tg][0];
        const float t0e = __expf(-0.5f * y * y);
        const float y2 = y * y, y4 = y2 * y2, y8 = y4 * y4, y16 = y8 * y8;
        float va[8], vb[8], vc[8];
        if (wid < 8) {                         // k in [0,24)
            feat8_vals(t0e,                 y, 0,  va);
            feat8_vals(t0e * y8  * RSF8,    y, 8,  vb);
            feat8_vals(t0e * y16 * RSF16,   y, 16, vc);
            feat8_reduce_store(va, dst, 0,  lane);
            feat8_reduce_store(vb, dst, 8,  lane);
            feat8_reduce_store(vc, dst, 16, lane);
        } else {                               // k in [24,48)
            const float y24 = y16 * y8, y32 = y16 * y16, y40 = y32 * y8;
            feat8_vals(t0e * y24 * RSF24,   y, 24, va);
            feat8_vals(t0e * y32 * RSF32,   y, 32, vb);
            feat8_vals(t0e * y40 * RSF40,   y, 40, vc);
            feat8_reduce_store(va, dst, 24, lane);
            feat8_reduce_store(vb, dst, 32, lane);
            feat8_reduce_store(vc, dst, 40, lane);
        }
    }

    // ---- flag: head h complete? (16 producers, incl. self) ----
    __syncthreads();
    if (tid == 0) {
        release_add(&g_cnt1[h][0]);
        acquire_wait(&g_cnt1[h][0], tgt1);
    }
    __syncthreads();

    // ========== Phase 2: scores + softmax + AV (8 rows per CTA) ==========
    {
        const int s0 = grp * 8;

        const float* psi = &g_psi[h][0][0];
        for (int i = tid; i < S * (KF / 4); i += 512) {
            int r = i / (KF / 4), c4 = i - r * (KF / 4);
            *(float4*)&Bm.Ps[r][c4 * 4] = *(const float4*)&psi[r * KF + c4 * 4];
        }
        const float* xl = &g_xln[h][0][0];
        for (int i = tid; i < S * (HD / 4); i += 512) {
            int r = i >> 3, c4 = i & 7;
            *(float4*)&Bm.Xs[r][c4 * 4] = *(const float4*)&xl[r * HD + c4 * 4];
        }
        __syncthreads();

        if (wid < 8) {
            // one row per warp: scores + softmax fully in registers
            const int row = s0 + wid;
            float acc[4] = {0.f, 0.f, 0.f, 0.f};
            #pragma unroll
            for (int kg = 0; kg < KF / 4; ++kg) {
                float4 rs = *(float4*)&Bm.Ps[row][kg * 4];       // broadcast
                #pragma unroll
                for (int tj = 0; tj < 4; ++tj) {
                    float4 rt = *(float4*)&Bm.Ps[lane + 32 * tj][kg * 4];  // stride 52: conflict-free
                    acc[tj] = fmaf(rs.x, rt.x, acc[tj]);
                    acc[tj] = fmaf(rs.y, rt.y, acc[tj]);
                    acc[tj] = fmaf(rs.z, rt.z, acc[tj]);
                    acc[tj] = fmaf(rs.w, rt.w, acc[tj]);
                }
            }
            #pragma unroll
            for (int tj = 0; tj < 4; ++tj) acc[tj] *= (1.0f / 32.0f);

            float m = warpmax(fmaxf(fmaxf(acc[0], acc[1]), fmaxf(acc[2], acc[3])));
            float sum = 0.f;
            #pragma unroll
            for (int tj = 0; tj < 4; ++tj) { acc[tj] = __expf(acc[tj] - m); sum += acc[tj]; }
            sum = warpsum(sum);
            const float inv = 1.0f / sum;
            #pragma unroll
            for (int tj = 0; tj < 4; ++tj) Bm.Sc[wid][lane + 32 * tj] = acc[tj] * inv;
        }
        __syncthreads();

        // AV split across all 16 warps: warp (r = wid&7, half = wid>>3) sums 64 t's
        {
            const int r = wid & 7, half = wid >> 3;
            float o = 0.f;
            #pragma unroll
            for (int t4 = half * 16; t4 < half * 16 + 16; ++t4) {
                float4 p4 = *(float4*)&Bm.Sc[r][t4 * 4];          // broadcast
                o = fmaf(p4.x, Bm.Xs[t4 * 4 + 0][lane], o);
                o = fmaf(p4.y, Bm.Xs[t4 * 4 + 1][lane], o);
                o = fmaf(p4.z, Bm.Xs[t4 * 4 + 2][lane], o);
                o = fmaf(p4.w, Bm.Xs[t4 * 4 + 3][lane], o);
            }
            Bm.Pav[half][r][lane] = o;
        }
        __syncthreads();

        if (wid < 8)
            g_cat[s0 + wid][h * HD + lane] = Bm.Pav[0][wid][lane] + Bm.Pav[1][wid][lane];
    }

    // ---- flag: token group grp complete? (8 producers, incl. self) ----
    __syncthreads();
    if (tid == 0) {
        release_add(&g_cnt2[grp][0]);
        acquire_wait(&g_cnt2[grp][0], tgt2);
    }
    __syncthreads();

    // ===================== Phase 3: out-projection ===========================
    {
        const int t0 = grp * BT;
        const int d0 = h * 32;

        for (int i = tid; i < BT * 64; i += 512) {
            int r = i >> 6, c4 = i & 63;
            *(float4*)&A.As[r][c4 * 4] = *(const float4*)&g_cat[t0 + r][c4 * 4];
        }
        for (int i = tid; i < HD * 64; i += 512) {
            int r = i >> 6, c4 = i & 63;
            *(float4*)&A.Bs[r][c4 * 4] = *(const float4*)&w_out[(d0 + r) * Dm + c4 * 4];
        }
        __syncthreads();

        {
            const int kq = wid >> 2, tp = wid & 3;
            float a0 = 0.f, a1 = 0.f;
            #pragma unroll
            for (int k4 = kq * 16; k4 < kq * 16 + 16; ++k4) {
                float4 bv = *(float4*)&A.Bs[lane][k4 * 4];
                float4 x0 = *(float4*)&A.As[tp * 2 + 0][k4 * 4];
                float4 x1 = *(float4*)&A.As[tp * 2 + 1][k4 * 4];
                a0 = fmaf(x0.x, bv.x, a0); a0 = fmaf(x0.y, bv.y, a0);
                a0 = fmaf(x0.z, bv.z, a0); a0 = fmaf(x0.w, bv.w, a0);
                a1 = fmaf(x1.x, bv.x, a1); a1 = fmaf(x1.y, bv.y, a1);
                a1 = fmaf(x1.z, bv.z, a1); a1 = fmaf(x1.w, bv.w, a1);
            }
            A.Pp[kq][tp * 2 + 0][lane] = a0;
            A.Pp[kq][tp * 2 + 1][lane] = a1;
        }
        __syncthreads();

        if (wid < 8) {
            const int tok = wid;
            float acc = A.Pp[0][tok][lane] + A.Pp[1][tok][lane]
                      + A.Pp[2][tok][lane] + A.Pp[3][tok][lane]
                      + b_out[d0 + lane];
            out[(t0 + tok) * Dm + d0 + lane] = acc;
        }
    }
}

// ---------------------------------------------------------------------------
extern "C" void kernel_launch(void* const* d_in, const int* in_sizes, int n_in,
                              void* d_out, int out_size) {
    const float* inp   = (const float*)d_in[0];
    const float* w_in  = (const float*)d_in[1];
    const float* b_in  = (const float*)d_in[2];
    const float* ln_g  = (const float*)d_in[3];
    const float* ln_b  = (const float*)d_in[4];
    const float* w_out = (const float*)d_in[5];
    const float* b_out = (const float*)d_in[6];
    float* out = (float*)d_out;

    kFused<<<128, 512>>>(inp, w_in, b_in, ln_g, ln_b, w_out, b_out, out);
}